// round 14
// baseline (speedup 1.0000x reference)
#include <cuda_runtime.h>
#include <cstdint>

// Problem constants
#define NSEG 6
#define NCH  512
#define NPOS 16384     // 128*128
#define NBINS 16
#define GEMV_GRID 740  // 148 SMs x 5 blocks (launch_bounds(256,5)) -> all resident

#define POOL_TILES 1536        // 4 chunks x 384 (6 seg x 32 cq x 2 half)
#define TILES_PER_CHUNK 384
#define FCA_TILES 6144         // 4 chunks x 1536 (6 seg x 256 rowblocks)

// ---------------- device scratch (no allocation allowed) ----------------
__device__ unsigned g_mbits[NSEG * 512];     // bit-packed mask, 512 u32/segment
__device__ float    g_fm[NSEG * NPOS];       // float 0/1 mask per position
__device__ int      g_posA[NSEG * NBINS];    // bin window start (position)
__device__ int      g_posB[NSEG * NBINS];    // bin window end (exclusive)
__device__ float    g_rdenom[NSEG * NBINS];  // 1/denom per bin
__device__ float    g_ys[NSEG * NCH * NBINS];
__device__ float    g_h1p[4][NSEG * 2048];   // fcA partials (K-split 4)
__device__ float    g_h2p[4][NSEG * 512];    // fcB partials (K-split 4)
__device__ float    g_w0[NSEG * 512];
__device__ unsigned g_cnt[4];                // pool-quarter completion counters
__device__ unsigned          g_count;        // fcBCT barrier arrivals
__device__ volatile unsigned g_gen;          // fcBCT barrier generation (monotonic)

// ---------------- K0: prep = mask + fm + scan + bin boundaries ----------
__global__ void __launch_bounds__(512) k_prep(const int* __restrict__ parsing)
{
    const int s = blockIdx.x;
    const int tid = threadIdx.x;
    __shared__ int ssum[512];
    __shared__ int sstart[NBINS], send[NBINS];

    if (s == 0 && tid < 4) g_cnt[tid] = 0;   // reset pipeline counters (stream-ordered)

    const int4* __restrict__ pv = (const int4*)(parsing + s * 65536); // [256,256]
    const int base = tid * 32;

    int cnt = 0;
    unsigned mw = 0;
    const int h = base >> 7;
    const int w0 = base & 127;
#pragma unroll
    for (int j = 0; j < 32; j += 2) {
        int w = w0 + j;
        int4 v = pv[h * 128 + (w >> 1)];
        int m0 = (v.x != 0);
        int m1 = (v.z != 0);
        cnt += m0 + m1;
        mw |= ((unsigned)m0) << j;
        mw |= ((unsigned)m1) << (j + 1);
    }
    g_mbits[s * 512 + tid] = mw;

    {
        float4* fmv = (float4*)(g_fm + s * NPOS + base);
#pragma unroll
        for (int q = 0; q < 8; q++) {
            int qq = q << 2;
            float4 f;
            f.x = ((mw >> qq)       & 1u) ? 1.f : 0.f;
            f.y = ((mw >> (qq + 1)) & 1u) ? 1.f : 0.f;
            f.z = ((mw >> (qq + 2)) & 1u) ? 1.f : 0.f;
            f.w = ((mw >> (qq + 3)) & 1u) ? 1.f : 0.f;
            fmv[q] = f;
        }
    }

    ssum[tid] = cnt;
    __syncthreads();
    for (int off = 1; off < 512; off <<= 1) {
        int v = (tid >= off) ? ssum[tid - off] : 0;
        __syncthreads();
        ssum[tid] += v;
        __syncthreads();
    }
    const int incl = ssum[tid];
    const int L    = ssum[511];
    const int exc  = incl - cnt;

    if (tid < NBINS) {
        int k  = tid;
        int st = (k * L) >> 4;
        int en = ((k + 1) * L + 15) >> 4;
        sstart[k] = st;
        send[k]   = en;
        int d = en - st; if (d < 1) d = 1;
        g_rdenom[s * NBINS + k] = 1.0f / (float)d;
        g_posA[s * NBINS + k] = 0;
        g_posB[s * NBINS + k] = 0;
    }
    __syncthreads();

    int r = exc;
#pragma unroll 1
    for (int j = 0; j < 32; j++) {
        if ((mw >> j) & 1u) {
            int p = base + j;
            for (int k = 0; k < NBINS; k++) {
                if (r == sstart[k])   g_posA[s * NBINS + k] = p;
                if (r + 1 == send[k]) g_posB[s * NBINS + k] = p + 1;
            }
            r++;
        }
    }
}

// ---------------- packed f32x2 FMA ----------------
__device__ __forceinline__ void ffma2(unsigned long long& acc,
                                      unsigned long long v,
                                      unsigned long long m)
{
    asm("fma.rn.f32x2 %0, %1, %2, %0;" : "+l"(acc) : "l"(v), "l"(m));
}
#define ULL(f4part) (*(const unsigned long long*)&(f4part))

__device__ __forceinline__ float dot4(float4 a, float4 b, float acc)
{
    acc = fmaf(a.x, b.x, acc);
    acc = fmaf(a.y, b.y, acc);
    acc = fmaf(a.z, b.z, acc);
    acc = fmaf(a.w, b.w, acc);
    return acc;
}
__device__ __forceinline__ float4 add4(float4 a, float4 b)
{ return make_float4(a.x + b.x, a.y + b.y, a.z + b.z, a.w + b.w); }

__device__ __forceinline__ float warp_red(float a)
{
#pragma unroll
    for (int o = 16; o; o >>= 1) a += __shfl_xor_sync(0xffffffffu, a, o);
    return a;
}

// ---------------- K1: fused pool -> fcA with device-side pipelining ------
// grid = POOL_TILES + FCA_TILES = 7680 blocks, 256 threads.
// bids [0,1536): pool tiles, chunk-major; each = 8 bins x 4 channels.
// bids [1536,7680): fcA tiles, chunk-major; spin until chunk's pool done.
__global__ void __launch_bounds__(256) k_poolfcA(const float* __restrict__ xs,
                                                 const float* __restrict__ W)
{
    __shared__ float4 sx[512];                // fcA x-tile (8 KB)
    const int tid  = threadIdx.x;
    const int wid  = tid >> 5;
    const int lane = tid & 31;
    const int bid  = blockIdx.x;

    if (bid < POOL_TILES) {
        // ---------- pool tile ----------
        const int chunk   = bid / TILES_PER_CHUNK;
        const int r       = bid - chunk * TILES_PER_CHUNK;   // 0..383
        const int s       = r >> 6;                          // /64
        const int r2      = r & 63;
        const int cqLocal = r2 >> 1;
        const int half    = r2 & 1;
        const int cq      = chunk * 32 + cqLocal;
        const int c0      = cq * 4;
        const int bin     = half * 8 + wid;

        const int lo = g_posA[s * NBINS + bin];
        const int hi = g_posB[s * NBINS + bin];

        const size_t chbase = ((size_t)(s * NCH + c0)) << 14;
        const float4* __restrict__ xa4 = (const float4*)(xs + chbase);
        const float4* __restrict__ xb4 = xa4 + (NPOS >> 2);
        const float4* __restrict__ xc4 = xb4 + (NPOS >> 2);
        const float4* __restrict__ xd4 = xc4 + (NPOS >> 2);
        const float4* __restrict__ fm4 = (const float4*)(g_fm + s * NPOS);

        const int ilo2 = (lo + 3) >> 2;
        const int ihi2 = hi >> 2;

        unsigned long long accA = 0, accB = 0, accC = 0, accD = 0;
        float eA = 0.f, eB = 0.f, eC = 0.f, eD = 0.f;

        for (int i = ilo2 + lane; i < ihi2; i += 32) {
            float4 f0 = fm4[i];
            float4 a0 = xa4[i];
            float4 b0 = xb4[i];
            float4 c0v = xc4[i];
            float4 d0 = xd4[i];
            ffma2(accA, ULL(a0.x), ULL(f0.x));
            ffma2(accA, ULL(a0.z), ULL(f0.z));
            ffma2(accB, ULL(b0.x), ULL(f0.x));
            ffma2(accB, ULL(b0.z), ULL(f0.z));
            ffma2(accC, ULL(c0v.x), ULL(f0.x));
            ffma2(accC, ULL(c0v.z), ULL(f0.z));
            ffma2(accD, ULL(d0.x), ULL(f0.x));
            ffma2(accD, ULL(d0.z), ULL(f0.z));
        }

        if (lane == 0) {
            for (int e = (lo >> 2); e < ilo2; e++) {
                float4 fa = fm4[e];
                float4 va = xa4[e];
                float4 vb = xb4[e];
                float4 vc = xc4[e];
                float4 vd = xd4[e];
                int p = e << 2;
                float m0 = (p     >= lo && p     < hi) ? fa.x : 0.f;
                float m1 = (p + 1 >= lo && p + 1 < hi) ? fa.y : 0.f;
                float m2 = (p + 2 >= lo && p + 2 < hi) ? fa.z : 0.f;
                float m3 = (p + 3 >= lo && p + 3 < hi) ? fa.w : 0.f;
                eA += va.x * m0 + va.y * m1 + va.z * m2 + va.w * m3;
                eB += vb.x * m0 + vb.y * m1 + vb.z * m2 + vb.w * m3;
                eC += vc.x * m0 + vc.y * m1 + vc.z * m2 + vc.w * m3;
                eD += vd.x * m0 + vd.y * m1 + vd.z * m2 + vd.w * m3;
            }
        }
        if (lane == 1) {
            int e0 = (ihi2 > ilo2) ? ihi2 : ilo2;
            for (int e = e0; e < ((hi + 3) >> 2); e++) {
                float4 fa = fm4[e];
                float4 va = xa4[e];
                float4 vb = xb4[e];
                float4 vc = xc4[e];
                float4 vd = xd4[e];
                int p = e << 2;
                float m0 = (p     >= lo && p     < hi) ? fa.x : 0.f;
                float m1 = (p + 1 >= lo && p + 1 < hi) ? fa.y : 0.f;
                float m2 = (p + 2 >= lo && p + 2 < hi) ? fa.z : 0.f;
                float m3 = (p + 3 >= lo && p + 3 < hi) ? fa.w : 0.f;
                eA += va.x * m0 + va.y * m1 + va.z * m2 + va.w * m3;
                eB += vb.x * m0 + vb.y * m1 + vb.z * m2 + vb.w * m3;
                eC += vc.x * m0 + vc.y * m1 + vc.z * m2 + vc.w * m3;
                eD += vd.x * m0 + vd.y * m1 + vd.z * m2 + vd.w * m3;
            }
        }

        float2 a2 = *(float2*)&accA;
        float2 b2 = *(float2*)&accB;
        float2 c2 = *(float2*)&accC;
        float2 d2 = *(float2*)&accD;
        float rA = a2.x + a2.y + eA;
        float rB = b2.x + b2.y + eB;
        float rC = c2.x + c2.y + eC;
        float rD = d2.x + d2.y + eD;
#pragma unroll
        for (int o = 16; o; o >>= 1) {
            rA += __shfl_xor_sync(0xffffffffu, rA, o);
            rB += __shfl_xor_sync(0xffffffffu, rB, o);
            rC += __shfl_xor_sync(0xffffffffu, rC, o);
            rD += __shfl_xor_sync(0xffffffffu, rD, o);
        }
        if (lane == 0) {
            float rd = g_rdenom[s * NBINS + bin];
            float* yb = g_ys + s * (NCH * NBINS) + c0 * NBINS + bin;
            yb[0]         = rA * rd;
            yb[NBINS]     = rB * rd;
            yb[2 * NBINS] = rC * rd;
            yb[3 * NBINS] = rD * rd;
        }

        // signal chunk completion
        __syncthreads();
        if (tid == 0) {
            __threadfence();
            atomicAdd(&g_cnt[chunk], 1u);
        }
    } else {
        // ---------- fcA tile ----------
        const int bid2  = bid - POOL_TILES;
        const int chunk = bid2 / 1536;
        const int r     = bid2 - chunk * 1536;
        const int s     = r >> 8;
        const int row   = (r & 255) * 8 + wid;

        // wait until this chunk's ys quarter is complete
        if (tid == 0) {
            int backoff = 32;
            while (*((volatile unsigned*)&g_cnt[chunk]) < TILES_PER_CHUNK) {
                __nanosleep(backoff);
                if (backoff < 1024) backoff <<= 1;
            }
            __threadfence();   // acquire
        }
        __syncthreads();

        const float4* __restrict__ xv = (const float4*)(g_ys + s * 8192 + chunk * 2048);
        for (int i = tid; i < 512; i += 256) sx[i] = xv[i];
        __syncthreads();

        const float4* __restrict__ wv =
            (const float4*)(W + (size_t)(s * 2048 + row) * 8192 + chunk * 2048);

        float a0 = 0.f, a1 = 0.f, a2 = 0.f, a3 = 0.f;
#pragma unroll 2
        for (int t = 0; t < 4; t++) {
            const int b = t * 128 + lane;
            float4 w0 = wv[b], w1 = wv[b + 32], w2 = wv[b + 64], w3 = wv[b + 96];
            a0 = dot4(w0, sx[b], a0);
            a1 = dot4(w1, sx[b + 32], a1);
            a2 = dot4(w2, sx[b + 64], a2);
            a3 = dot4(w3, sx[b + 96], a3);
        }
        float a = warp_red((a0 + a1) + (a2 + a3));
        if (lane == 0) g_h1p[chunk][s * 2048 + row] = a;
    }
}

// Grid-wide barrier for k_fcBCT (all blocks resident).
__device__ __forceinline__ void grid_barrier()
{
    __syncthreads();
    __threadfence();
    if (threadIdx.x == 0) {
        unsigned gen = g_gen;
        if (atomicAdd(&g_count, 1u) == gridDim.x - 1) {
            g_count = 0;
            __threadfence();
            g_gen = gen + 1;            // release
        } else {
            int backoff = 32;
            while (g_gen == gen) {
                __nanosleep(backoff);
                if (backoff < 256) backoff <<= 1;
            }
        }
        __threadfence();                // acquire
    }
    __syncthreads();
}

// ---------------- fused fcB (Ksplit4) -> fcC -> block-local tail ----------
// 740 persistent blocks x 256 threads; 2 grid barriers.
__global__ void __launch_bounds__(256, 5) k_fcBCT(
    const float* __restrict__ fcB_w, const float* __restrict__ bA,
    const float* __restrict__ fcC_w, const float* __restrict__ bB,
    const float* __restrict__ bC,
    const float* __restrict__ p1w, const float* __restrict__ p1b,
    const float* __restrict__ p2w, const float* __restrict__ p2b,
    const float* __restrict__ p3w, const float* __restrict__ p3b,
    float* __restrict__ out)
{
    __shared__ __align__(16) float smem[1024];   // 4 KB: sx(512) | tail sw0/sw1/sw2
    float4* sx = (float4*)smem;                  // 128 float4 = 512 floats
    const int tid  = threadIdx.x;
    const int wid  = tid >> 5;
    const int lane = tid & 31;

    // ---- phase fcB: 1536 tiles (6 seg x 4 chunks x 64 rowblocks), K-chunk 512
    for (int t = blockIdx.x; t < 1536; t += gridDim.x) {
        const int s     = t >> 8;
        const int rem   = t & 255;
        const int chunk = rem >> 6;
        const int row   = (rem & 63) * 8 + wid;

        __syncthreads();
        const int xoff = (s * 2048 + chunk * 512) >> 2;
        if (tid < 128) {
            const float4* q0 = ((const float4*)g_h1p[0]) + xoff;
            const float4* q1 = ((const float4*)g_h1p[1]) + xoff;
            const float4* q2 = ((const float4*)g_h1p[2]) + xoff;
            const float4* q3 = ((const float4*)g_h1p[3]) + xoff;
            const float4* bb = ((const float4*)bA) + xoff;
            sx[tid] = add4(add4(add4(q0[tid], q1[tid]), add4(q2[tid], q3[tid])), bb[tid]);
        }
        __syncthreads();

        const float4* __restrict__ wv =
            (const float4*)(fcB_w + (size_t)(s * 512 + row) * 2048 + chunk * 512);
        float a0 = dot4(wv[lane],      sx[lane],      0.f);
        float a1 = dot4(wv[lane + 32], sx[lane + 32], 0.f);
        float a2 = dot4(wv[lane + 64], sx[lane + 64], 0.f);
        float a3 = dot4(wv[lane + 96], sx[lane + 96], 0.f);
        float a = warp_red((a0 + a1) + (a2 + a3));
        if (lane == 0) g_h2p[chunk][s * 512 + row] = a;
    }
    grid_barrier();

    // ---- phase fcC: 384 tiles (6 seg x 64 rowblocks), K=512
    for (int t = blockIdx.x; t < 384; t += gridDim.x) {
        const int s   = t >> 6;
        const int row = (t & 63) * 8 + wid;

        __syncthreads();
        const int xoff = (s * 512) >> 2;
        if (tid < 128) {
            const float4* q0 = ((const float4*)g_h2p[0]) + xoff;
            const float4* q1 = ((const float4*)g_h2p[1]) + xoff;
            const float4* q2 = ((const float4*)g_h2p[2]) + xoff;
            const float4* q3 = ((const float4*)g_h2p[3]) + xoff;
            const float4* bb = ((const float4*)bB) + xoff;
            sx[tid] = add4(add4(add4(q0[tid], q1[tid]), add4(q2[tid], q3[tid])), bb[tid]);
        }
        __syncthreads();

        const float4* __restrict__ wv = (const float4*)(fcC_w + (size_t)(s * 512 + row) * 512);
        float a0 = dot4(wv[lane],      sx[lane],      0.f);
        float a1 = dot4(wv[lane + 32], sx[lane + 32], 0.f);
        float a2 = dot4(wv[lane + 64], sx[lane + 64], 0.f);
        float a3 = dot4(wv[lane + 96], sx[lane + 96], 0.f);
        float a = warp_red((a0 + a1) + (a2 + a3));
        if (lane == 0) {
            float r = a + bC[s * 512 + row];
            g_w0[s * 512 + row] = r;
            out[s * 960 + row]  = r;
        }
    }
    grid_barrier();

    // ---- tail: blocks 0..5 each run p1->p2->p3 block-locally; rest exit ----
    if (blockIdx.x >= NSEG) return;
    {
        const int s = blockIdx.x;
        float* sw0 = smem;            // 512
        float* sw1 = sw0 + 512;       // 256
        float* sw2 = sw1 + 256;       // 128

        __syncthreads();
        for (int i = tid; i < 512; i += 256) sw0[i] = g_w0[s * 512 + i];
        __syncthreads();

        // p1: 256 rows, K=512
        for (int row = wid; row < 256; row += 8) {
            const float4* wr = (const float4*)(p1w + (size_t)row * 512);
            const float4* xr = (const float4*)sw0;
            float a0 = dot4(wr[lane],      xr[lane],      0.f);
            float a1 = dot4(wr[lane + 32], xr[lane + 32], 0.f);
            float a2 = dot4(wr[lane + 64], xr[lane + 64], 0.f);
            float a3 = dot4(wr[lane + 96], xr[lane + 96], 0.f);
            float a = warp_red((a0 + a1) + (a2 + a3));
            if (lane == 0) {
                float r = a + p1b[row];
                sw1[row] = r;
                out[s * 960 + 512 + row] = r;
            }
        }
        __syncthreads();
        // p2: 128 rows, K=256
        for (int row = wid; row < 128; row += 8) {
            const float4* wr = (const float4*)(p2w + (size_t)row * 256);
            const float4* xr = (const float4*)sw1;
            float a0 = dot4(wr[lane],      xr[lane],      0.f);
            float a1 = dot4(wr[lane + 32], xr[lane + 32], 0.f);
            float a = warp_red(a0 + a1);
            if (lane == 0) {
                float r = a + p2b[row];
                sw2[row] = r;
                out[s * 960 + 768 + row] = r;
            }
        }
        __syncthreads();
        // p3: 64 rows, K=128
        for (int row = wid; row < 64; row += 8) {
            const float4* wr = (const float4*)(p3w + (size_t)row * 128);
            const float4* xr = (const float4*)sw2;
            float a = warp_red(dot4(wr[lane], xr[lane], 0.f));
            if (lane == 0) out[s * 960 + 896 + row] = a + p3b[row];
        }
    }
}

// ---------------- launch: prep -> poolfcA (pipelined) -> fcBCT ----------
extern "C" void kernel_launch(void* const* d_in, const int* in_sizes, int n_in,
                              void* d_out, int out_size)
{
    const float* xs      = (const float*)d_in[0];
    const int*   parsing = (const int*)  d_in[1];
    const float* fcA_w   = (const float*)d_in[2];
    const float* fcA_b   = (const float*)d_in[3];
    const float* fcB_w   = (const float*)d_in[4];
    const float* fcB_b   = (const float*)d_in[5];
    const float* fcC_w   = (const float*)d_in[6];
    const float* fcC_b   = (const float*)d_in[7];
    const float* p1_w    = (const float*)d_in[8];
    const float* p1_b    = (const float*)d_in[9];
    const float* p2_w    = (const float*)d_in[10];
    const float* p2_b    = (const float*)d_in[11];
    const float* p3_w    = (const float*)d_in[12];
    const float* p3_b    = (const float*)d_in[13];
    float* out = (float*)d_out;

    k_prep<<<NSEG, 512>>>(parsing);                          // #0 (also resets g_cnt)
    k_poolfcA<<<POOL_TILES + FCA_TILES, 256>>>(xs, fcA_w);   // #1 (pipelined)
    k_fcBCT<<<GEMV_GRID, 256>>>(fcB_w, fcA_b, fcC_w, fcB_b, fcC_b,
                                p1_w, p1_b, p2_w, p2_b, p3_w, p3_b, out);  // #2
}

// round 15
// speedup vs baseline: 1.1884x; 1.1884x over previous
#include <cuda_runtime.h>
#include <cstdint>

// Problem constants
#define NSEG 6
#define NCH  512
#define NPOS 16384     // 128*128
#define NBINS 16
#define GEMV_GRID 740  // 148 SMs x 5 blocks (launch_bounds(256,5)) -> all resident

// ---------------- device scratch (no allocation allowed) ----------------
__device__ float    g_fm[NSEG * NPOS];       // float 0/1 mask per position
__device__ int      g_posA[NSEG * NBINS];    // bin window start (position)
__device__ int      g_posB[NSEG * NBINS];    // bin window end (exclusive)
__device__ float    g_rdenom[NSEG * NBINS];  // 1/denom per bin
__device__ float    g_ys[NSEG * NCH * NBINS];
__device__ float    g_h1p[4][NSEG * 2048];   // fcA partials (K-split 4)
__device__ float    g_h2p[4][NSEG * 512];    // fcB partials (K-split 4)
__device__ float    g_w0[NSEG * 512];
__device__ unsigned          g_count;        // fcBCT barrier arrivals
__device__ volatile unsigned g_gen;          // fcBCT barrier generation (monotonic)

// ---------------- K0: prep = mask + fm + scan + rank-select bins --------
// grid = 6 blocks, 512 threads, 32 positions/thread.
__global__ void __launch_bounds__(512) k_prep(const int* __restrict__ parsing)
{
    const int s    = blockIdx.x;
    const int tid  = threadIdx.x;
    const int wid  = tid >> 5;
    const int lane = tid & 31;

    __shared__ unsigned smw[512];     // mask words
    __shared__ int      sincl[512];   // inclusive scan of popcounts
    __shared__ int      swarp[16];    // per-warp totals

    const int4* __restrict__ pv = (const int4*)(parsing + s * 65536); // [256,256]
    const int base = tid * 32;   // 32 consecutive positions, same h row

    // pass 1: nearest 256->128 is src index*2; int4 covers 2 sampled positions.
    unsigned mw = 0;
    const int h  = base >> 7;
    const int w0 = base & 127;
#pragma unroll
    for (int j = 0; j < 32; j += 2) {
        int w = w0 + j;
        int4 v = pv[h * 128 + (w >> 1)];
        unsigned m0 = (v.x != 0), m1 = (v.z != 0);
        mw |= m0 << j;
        mw |= m1 << (j + 1);
    }
    smw[tid] = mw;

    // float 0/1 mask, 8 float4 stores
    {
        float4* fmv = (float4*)(g_fm + s * NPOS + base);
#pragma unroll
        for (int q = 0; q < 8; q++) {
            int qq = q << 2;
            float4 f;
            f.x = ((mw >> qq)       & 1u) ? 1.f : 0.f;
            f.y = ((mw >> (qq + 1)) & 1u) ? 1.f : 0.f;
            f.z = ((mw >> (qq + 2)) & 1u) ? 1.f : 0.f;
            f.w = ((mw >> (qq + 3)) & 1u) ? 1.f : 0.f;
            fmv[q] = f;
        }
    }

    // two-level scan of popcounts (warp shuffle + warp-total scan)
    int incl = __popc(mw);
#pragma unroll
    for (int o = 1; o < 32; o <<= 1) {
        int v = __shfl_up_sync(0xffffffffu, incl, o);
        if (lane >= o) incl += v;
    }
    if (lane == 31) swarp[wid] = incl;
    __syncthreads();
    if (tid < 16) {
        int v = swarp[tid];
#pragma unroll
        for (int o = 1; o < 16; o <<= 1) {
            int u = __shfl_up_sync(0x0000ffffu, v, o);
            if (tid >= o) v += u;
        }
        swarp[tid] = v;
    }
    __syncthreads();
    if (wid > 0) incl += swarp[wid - 1];
    sincl[tid] = incl;
    __syncthreads();

    const int L = swarp[15];

    // rank-select: threads 0..15 resolve bin starts, 16..31 resolve bin ends.
    if (tid < 32) {
        const int  k       = tid & 15;
        const bool isStart = tid < 16;
        const int st = (k * L) >> 4;                 // floor(k*L/16)
        const int en = ((k + 1) * L + 15) >> 4;      // ceil((k+1)*L/16)

        if (isStart) {
            int d = en - st; if (d < 1) d = 1;
            g_rdenom[s * NBINS + k] = 1.0f / (float)d;
        }

        if (en <= st) {      // empty bin -> empty window
            if (isStart) g_posA[s * NBINS + k] = 0;
            else         g_posB[s * NBINS + k] = 0;
        } else {
            const int target = isStart ? st : (en - 1);   // 0-based rank
            // binary search: minimal t with sincl[t] > target
            int lo = 0, hi = 512;
            while (lo < hi) {
                int mid = (lo + hi) >> 1;
                if (sincl[mid] > target) hi = mid; else lo = mid + 1;
            }
            const int t   = lo;
            const int exc = (t > 0) ? sincl[t - 1] : 0;
            const int r   = target - exc;                 // rank within word
            const int bit = __fns(smw[t], 0, r + 1);      // (r+1)-th set bit
            const int pos = t * 32 + bit;
            if (isStart) g_posA[s * NBINS + k] = pos;
            else         g_posB[s * NBINS + k] = pos + 1;
        }
    }
}

// ---------------- packed f32x2 FMA ----------------
__device__ __forceinline__ void ffma2(unsigned long long& acc,
                                      unsigned long long v,
                                      unsigned long long m)
{
    asm("fma.rn.f32x2 %0, %1, %2, %0;" : "+l"(acc) : "l"(v), "l"(m));
}
#define ULL(f4part) (*(const unsigned long long*)&(f4part))

// ---------------- K1: masked adaptive pool, 4 channels / warp ------------
// grid = NSEG * 128 blocks (channel quads), 512 threads = 16 warps (bin each).
__global__ void __launch_bounds__(512, 2) k_pool(const float* __restrict__ xs)
{
    const int bid  = blockIdx.x;          // s*128 + cq
    const int s    = bid >> 7;
    const int cq   = bid & 127;
    const int c0   = cq * 4;
    const int warp = threadIdx.x >> 5;
    const int lane = threadIdx.x & 31;

    const int lo = g_posA[s * NBINS + warp];
    const int hi = g_posB[s * NBINS + warp];

    const size_t chbase = ((size_t)(s * NCH + c0)) << 14;
    const float4* __restrict__ xa4 = (const float4*)(xs + chbase);
    const float4* __restrict__ xb4 = xa4 + (NPOS >> 2);
    const float4* __restrict__ xc4 = xb4 + (NPOS >> 2);
    const float4* __restrict__ xd4 = xc4 + (NPOS >> 2);
    const float4* __restrict__ fm4 = (const float4*)(g_fm + s * NPOS);

    const int ilo2 = (lo + 3) >> 2;       // first fully-inside float4
    const int ihi2 = hi >> 2;             // end of fully-inside float4s

    unsigned long long accA = 0, accB = 0, accC = 0, accD = 0;
    float eA = 0.f, eB = 0.f, eC = 0.f, eD = 0.f;

    for (int i = ilo2 + lane; i < ihi2; i += 32) {
        float4 f0 = fm4[i];
        float4 a0 = xa4[i];
        float4 b0 = xb4[i];
        float4 c0v = xc4[i];
        float4 d0 = xd4[i];
        ffma2(accA, ULL(a0.x), ULL(f0.x));
        ffma2(accA, ULL(a0.z), ULL(f0.z));
        ffma2(accB, ULL(b0.x), ULL(f0.x));
        ffma2(accB, ULL(b0.z), ULL(f0.z));
        ffma2(accC, ULL(c0v.x), ULL(f0.x));
        ffma2(accC, ULL(c0v.z), ULL(f0.z));
        ffma2(accD, ULL(d0.x), ULL(f0.x));
        ffma2(accD, ULL(d0.z), ULL(f0.z));
    }

    // edge float4s (≤1 each side) with explicit window checks
    if (lane == 0) {
        for (int e = (lo >> 2); e < ilo2; e++) {
            float4 fa = fm4[e];
            float4 va = xa4[e];
            float4 vb = xb4[e];
            float4 vc = xc4[e];
            float4 vd = xd4[e];
            int p = e << 2;
            float m0 = (p     >= lo && p     < hi) ? fa.x : 0.f;
            float m1 = (p + 1 >= lo && p + 1 < hi) ? fa.y : 0.f;
            float m2 = (p + 2 >= lo && p + 2 < hi) ? fa.z : 0.f;
            float m3 = (p + 3 >= lo && p + 3 < hi) ? fa.w : 0.f;
            eA += va.x * m0 + va.y * m1 + va.z * m2 + va.w * m3;
            eB += vb.x * m0 + vb.y * m1 + vb.z * m2 + vb.w * m3;
            eC += vc.x * m0 + vc.y * m1 + vc.z * m2 + vc.w * m3;
            eD += vd.x * m0 + vd.y * m1 + vd.z * m2 + vd.w * m3;
        }
    }
    if (lane == 1) {
        int e0 = (ihi2 > ilo2) ? ihi2 : ilo2;
        for (int e = e0; e < ((hi + 3) >> 2); e++) {
            float4 fa = fm4[e];
            float4 va = xa4[e];
            float4 vb = xb4[e];
            float4 vc = xc4[e];
            float4 vd = xd4[e];
            int p = e << 2;
            float m0 = (p     >= lo && p     < hi) ? fa.x : 0.f;
            float m1 = (p + 1 >= lo && p + 1 < hi) ? fa.y : 0.f;
            float m2 = (p + 2 >= lo && p + 2 < hi) ? fa.z : 0.f;
            float m3 = (p + 3 >= lo && p + 3 < hi) ? fa.w : 0.f;
            eA += va.x * m0 + va.y * m1 + va.z * m2 + va.w * m3;
            eB += vb.x * m0 + vb.y * m1 + vb.z * m2 + vb.w * m3;
            eC += vc.x * m0 + vc.y * m1 + vc.z * m2 + vc.w * m3;
            eD += vd.x * m0 + vd.y * m1 + vd.z * m2 + vd.w * m3;
        }
    }

    float2 a2 = *(float2*)&accA;
    float2 b2 = *(float2*)&accB;
    float2 c2 = *(float2*)&accC;
    float2 d2 = *(float2*)&accD;
    float rA = a2.x + a2.y + eA;
    float rB = b2.x + b2.y + eB;
    float rC = c2.x + c2.y + eC;
    float rD = d2.x + d2.y + eD;
#pragma unroll
    for (int o = 16; o; o >>= 1) {
        rA += __shfl_xor_sync(0xffffffffu, rA, o);
        rB += __shfl_xor_sync(0xffffffffu, rB, o);
        rC += __shfl_xor_sync(0xffffffffu, rC, o);
        rD += __shfl_xor_sync(0xffffffffu, rD, o);
    }
    if (lane == 0) {
        float rd = g_rdenom[s * NBINS + warp];
        float* yb = g_ys + s * (NCH * NBINS) + c0 * NBINS + warp;
        yb[0]         = rA * rd;
        yb[NBINS]     = rB * rd;
        yb[2 * NBINS] = rC * rd;
        yb[3 * NBINS] = rD * rd;
    }
}

// ---------------- helpers ----------------
__device__ __forceinline__ float dot4(float4 a, float4 b, float acc)
{
    acc = fmaf(a.x, b.x, acc);
    acc = fmaf(a.y, b.y, acc);
    acc = fmaf(a.z, b.z, acc);
    acc = fmaf(a.w, b.w, acc);
    return acc;
}
__device__ __forceinline__ float4 add4(float4 a, float4 b)
{ return make_float4(a.x + b.x, a.y + b.y, a.z + b.z, a.w + b.w); }

__device__ __forceinline__ float warp_red(float a)
{
#pragma unroll
    for (int o = 16; o; o >>= 1) a += __shfl_xor_sync(0xffffffffu, a, o);
    return a;
}

// Grid-wide barrier for k_fcBCT (all blocks resident).
__device__ __forceinline__ void grid_barrier()
{
    __syncthreads();
    __threadfence();
    if (threadIdx.x == 0) {
        unsigned gen = g_gen;
        if (atomicAdd(&g_count, 1u) == gridDim.x - 1) {
            g_count = 0;
            __threadfence();
            g_gen = gen + 1;            // release
        } else {
            int backoff = 32;
            while (g_gen == gen) {
                __nanosleep(backoff);
                if (backoff < 256) backoff <<= 1;
            }
        }
        __threadfence();                // acquire
    }
    __syncthreads();
}

// ---------------- fcA: 2048x8192 GEMV, K-split 4 (standalone, proven) ----
__global__ void __launch_bounds__(256) k_fcA(const float* __restrict__ W)
{
    __shared__ float4 sx[512];                // 2048-float chunk of ys
    const int bid   = blockIdx.x;
    const int s     = bid >> 10;
    const int rem   = bid & 1023;
    const int chunk = rem >> 8;
    const int row   = (rem & 255) * 8 + (threadIdx.x >> 5);
    const int lane  = threadIdx.x & 31;

    const float4* __restrict__ xv = (const float4*)(g_ys + s * 8192 + chunk * 2048);
    for (int i = threadIdx.x; i < 512; i += 256) sx[i] = xv[i];
    __syncthreads();

    const float4* __restrict__ wv =
        (const float4*)(W + (size_t)(s * 2048 + row) * 8192 + chunk * 2048);

    float a0 = 0.f, a1 = 0.f, a2 = 0.f, a3 = 0.f;
#pragma unroll 2
    for (int t = 0; t < 4; t++) {
        const int b = t * 128 + lane;
        float4 w0 = wv[b], w1 = wv[b + 32], w2 = wv[b + 64], w3 = wv[b + 96];
        a0 = dot4(w0, sx[b], a0);
        a1 = dot4(w1, sx[b + 32], a1);
        a2 = dot4(w2, sx[b + 64], a2);
        a3 = dot4(w3, sx[b + 96], a3);
    }
    float a = warp_red((a0 + a1) + (a2 + a3));
    if (lane == 0) g_h1p[chunk][s * 2048 + row] = a;
}

// ---------------- fused fcB (Ksplit4) -> fcC -> block-local tail ----------
// 740 persistent blocks x 256 threads; 2 grid barriers.
__global__ void __launch_bounds__(256, 5) k_fcBCT(
    const float* __restrict__ fcB_w, const float* __restrict__ bA,
    const float* __restrict__ fcC_w, const float* __restrict__ bB,
    const float* __restrict__ bC,
    const float* __restrict__ p1w, const float* __restrict__ p1b,
    const float* __restrict__ p2w, const float* __restrict__ p2b,
    const float* __restrict__ p3w, const float* __restrict__ p3b,
    float* __restrict__ out)
{
    __shared__ __align__(16) float smem[1024];   // 4 KB: sx(512) | tail sw0/sw1/sw2
    float4* sx = (float4*)smem;                  // 128 float4 = 512 floats
    const int tid  = threadIdx.x;
    const int wid  = tid >> 5;
    const int lane = tid & 31;

    // ---- phase fcB: 1536 tiles (6 seg x 4 chunks x 64 rowblocks), K-chunk 512
    for (int t = blockIdx.x; t < 1536; t += gridDim.x) {
        const int s     = t >> 8;
        const int rem   = t & 255;
        const int chunk = rem >> 6;
        const int row   = (rem & 63) * 8 + wid;

        __syncthreads();
        const int xoff = (s * 2048 + chunk * 512) >> 2;
        if (tid < 128) {
            const float4* q0 = ((const float4*)g_h1p[0]) + xoff;
            const float4* q1 = ((const float4*)g_h1p[1]) + xoff;
            const float4* q2 = ((const float4*)g_h1p[2]) + xoff;
            const float4* q3 = ((const float4*)g_h1p[3]) + xoff;
            const float4* bb = ((const float4*)bA) + xoff;
            sx[tid] = add4(add4(add4(q0[tid], q1[tid]), add4(q2[tid], q3[tid])), bb[tid]);
        }
        __syncthreads();

        const float4* __restrict__ wv =
            (const float4*)(fcB_w + (size_t)(s * 512 + row) * 2048 + chunk * 512);
        float a0 = dot4(wv[lane],      sx[lane],      0.f);
        float a1 = dot4(wv[lane + 32], sx[lane + 32], 0.f);
        float a2 = dot4(wv[lane + 64], sx[lane + 64], 0.f);
        float a3 = dot4(wv[lane + 96], sx[lane + 96], 0.f);
        float a = warp_red((a0 + a1) + (a2 + a3));
        if (lane == 0) g_h2p[chunk][s * 512 + row] = a;
    }
    grid_barrier();

    // ---- phase fcC: 384 tiles (6 seg x 64 rowblocks), K=512
    for (int t = blockIdx.x; t < 384; t += gridDim.x) {
        const int s   = t >> 6;
        const int row = (t & 63) * 8 + wid;

        __syncthreads();
        const int xoff = (s * 512) >> 2;
        if (tid < 128) {
            const float4* q0 = ((const float4*)g_h2p[0]) + xoff;
            const float4* q1 = ((const float4*)g_h2p[1]) + xoff;
            const float4* q2 = ((const float4*)g_h2p[2]) + xoff;
            const float4* q3 = ((const float4*)g_h2p[3]) + xoff;
            const float4* bb = ((const float4*)bB) + xoff;
            sx[tid] = add4(add4(add4(q0[tid], q1[tid]), add4(q2[tid], q3[tid])), bb[tid]);
        }
        __syncthreads();

        const float4* __restrict__ wv = (const float4*)(fcC_w + (size_t)(s * 512 + row) * 512);
        float a0 = dot4(wv[lane],      sx[lane],      0.f);
        float a1 = dot4(wv[lane + 32], sx[lane + 32], 0.f);
        float a2 = dot4(wv[lane + 64], sx[lane + 64], 0.f);
        float a3 = dot4(wv[lane + 96], sx[lane + 96], 0.f);
        float a = warp_red((a0 + a1) + (a2 + a3));
        if (lane == 0) {
            float r = a + bC[s * 512 + row];
            g_w0[s * 512 + row] = r;
            out[s * 960 + row]  = r;
        }
    }
    grid_barrier();

    // ---- tail: blocks 0..5 each run p1->p2->p3 block-locally; rest exit ----
    if (blockIdx.x >= NSEG) return;
    {
        const int s = blockIdx.x;
        float* sw0 = smem;            // 512
        float* sw1 = sw0 + 512;       // 256
        float* sw2 = sw1 + 256;       // 128

        __syncthreads();
        for (int i = tid; i < 512; i += 256) sw0[i] = g_w0[s * 512 + i];
        __syncthreads();

        // p1: 256 rows, K=512
        for (int row = wid; row < 256; row += 8) {
            const float4* wr = (const float4*)(p1w + (size_t)row * 512);
            const float4* xr = (const float4*)sw0;
            float a0 = dot4(wr[lane],      xr[lane],      0.f);
            float a1 = dot4(wr[lane + 32], xr[lane + 32], 0.f);
            float a2 = dot4(wr[lane + 64], xr[lane + 64], 0.f);
            float a3 = dot4(wr[lane + 96], xr[lane + 96], 0.f);
            float a = warp_red((a0 + a1) + (a2 + a3));
            if (lane == 0) {
                float r = a + p1b[row];
                sw1[row] = r;
                out[s * 960 + 512 + row] = r;
            }
        }
        __syncthreads();
        // p2: 128 rows, K=256
        for (int row = wid; row < 128; row += 8) {
            const float4* wr = (const float4*)(p2w + (size_t)row * 256);
            const float4* xr = (const float4*)sw1;
            float a0 = dot4(wr[lane],      xr[lane],      0.f);
            float a1 = dot4(wr[lane + 32], xr[lane + 32], 0.f);
            float a = warp_red(a0 + a1);
            if (lane == 0) {
                float r = a + p2b[row];
                sw2[row] = r;
                out[s * 960 + 768 + row] = r;
            }
        }
        __syncthreads();
        // p3: 64 rows, K=128
        for (int row = wid; row < 64; row += 8) {
            const float4* wr = (const float4*)(p3w + (size_t)row * 128);
            const float4* xr = (const float4*)sw2;
            float a = warp_red(dot4(wr[lane], xr[lane], 0.f));
            if (lane == 0) out[s * 960 + 896 + row] = a + p3b[row];
        }
    }
}

// ---------------- launch ----------------
extern "C" void kernel_launch(void* const* d_in, const int* in_sizes, int n_in,
                              void* d_out, int out_size)
{
    const float* xs      = (const float*)d_in[0];
    const int*   parsing = (const int*)  d_in[1];
    const float* fcA_w   = (const float*)d_in[2];
    const float* fcA_b   = (const float*)d_in[3];
    const float* fcB_w   = (const float*)d_in[4];
    const float* fcB_b   = (const float*)d_in[5];
    const float* fcC_w   = (const float*)d_in[6];
    const float* fcC_b   = (const float*)d_in[7];
    const float* p1_w    = (const float*)d_in[8];
    const float* p1_b    = (const float*)d_in[9];
    const float* p2_w    = (const float*)d_in[10];
    const float* p2_b    = (const float*)d_in[11];
    const float* p3_w    = (const float*)d_in[12];
    const float* p3_b    = (const float*)d_in[13];
    float* out = (float*)d_out;

    k_prep<<<NSEG, 512>>>(parsing);                  // #0  (rank-select bins)
    k_pool<<<NSEG * 128, 512>>>(xs);                 // #1  <- profiled (skip-5)
    k_fcA <<<NSEG * 256 * 4, 256>>>(fcA_w);          // #2
    k_fcBCT<<<GEMV_GRID, 256>>>(fcB_w, fcA_b, fcC_w, fcB_b, fcC_b,
                                p1_w, p1_b, p2_w, p2_b, p3_w, p3_b, out);  // #3
}